// round 16
// baseline (speedup 1.0000x reference)
#include <cuda_runtime.h>
#include <cuda_bf16.h>
#include <math.h>

#define NB    32
#define SL    20
#define DIM   256
#define BEAMW 4
#define G     128
#define NT    512
#define EPSC  1e-8f
#define LNEPS 1e-5f
#define NPOOL (NB * SL + 37 * NB * BEAMW)

// dynamic smem: 8 buffers of 64*72 bf16 (9216 B): AH0 AH1 AL0 AL1 BH0 BH1 BL0 BL1
#define BUFB 9216
#define OAH(b) ((b) * BUFB)
#define OAL(b) (18432 + (b) * BUFB)
#define OBH(b) (36864 + (b) * BUFB)
#define OBL(b) (55296 + (b) * BUFB)
#define SMEM_DYN 73728

// ---------------- static device scratch ----------------
__device__ float d_pool[NPOOL * DIM];
__device__ __nv_bfloat16 d_poolh[(NPOOL + 1) * DIM];   // hi mirror (+START row at NPOOL)
__device__ __nv_bfloat16 d_pooll[(NPOOL + 1) * DIM];   // lo mirror
__device__ int   d_tab[2][NB * BEAMW][SL];
__device__ int   d_p[2][NB * BEAMW];
__device__ int   d_q[2][NB * BEAMW];
__device__ int   d_asrc[2][128 * 3];       // laster/last/cur: >=0 pool row, -1 start, -2 zero
__device__ float d_cpart[3 * 128 * 256];   // conv partials ks3
__device__ float d_i1[2 * 128 * 1024];     // cell1 partials ks2
__device__ float d_c2[4 * 128 * 1024];     // cell2 partials ks4
__device__ float d_rs[128], d_ss[128];
__device__ float d_bscore[NB * BEAMW];
__device__ __nv_bfloat16 d_w1h[512 * 1024],  d_w1l[512 * 1024];
__device__ __nv_bfloat16 d_w2h[1024 * 1024], d_w2l[1024 * 1024];
__device__ __nv_bfloat16 d_wch[768 * 256],   d_wcl[768 * 256];
__device__ volatile unsigned g_flags[G];
__device__ volatile unsigned g_rel;
__device__ unsigned g_epbase = 0;          // persists across graph replays

// ---------------- flag-array grid barrier (replay-safe epochs) ----------------
__device__ __forceinline__ void gbar(unsigned& ep) {
    __syncthreads();
    int tid = threadIdx.x;
    int bid = blockIdx.x;
    if (tid == 0) {
        __threadfence();
        g_flags[bid] = ep;
    }
    if (bid == 0) {
        if (tid < G) {
            while (g_flags[tid] < ep) { }
        }
        __syncthreads();
        if (tid == 0) {
            __threadfence();
            g_rel = ep;
        }
    } else {
        if (tid == 0) {
            while (g_rel < ep) { }
            __threadfence();
        }
    }
    __syncthreads();
    ep++;
}

// ---------------- helpers ----------------
__device__ __forceinline__ float geluf(float x) {
    return 0.5f * x * (1.0f + erff(x * 0.7071067811865476f));
}
__device__ __forceinline__ float sigmoidf_(float x) {
    return 1.0f / (1.0f + expf(-x));
}
__device__ __forceinline__ float halfReduceSum(float v, float* sbuf) {
    int tid = threadIdx.x;
    #pragma unroll
    for (int o = 16; o > 0; o >>= 1) v += __shfl_down_sync(0xffffffffu, v, o);
    if ((tid & 31) == 0) sbuf[tid >> 5] = v;
    __syncthreads();
    int h = tid >> 8;
    float r = 0.f;
    #pragma unroll
    for (int w = 0; w < 8; w++) r += sbuf[h * 8 + w];
    __syncthreads();
    return r;
}
__device__ __forceinline__ unsigned smem_u32(const void* p) {
    unsigned a;
    asm("{ .reg .u64 t; cvta.to.shared.u64 t, %1; cvt.u32.u64 %0, t; }" : "=r"(a) : "l"(p));
    return a;
}
__device__ __forceinline__ void cvt2(float a, float b, unsigned& h, unsigned& l) {
    __nv_bfloat162 hh = __floats2bfloat162_rn(a, b);
    __nv_bfloat162 ll = __floats2bfloat162_rn(a - __bfloat162float(hh.x),
                                              b - __bfloat162float(hh.y));
    h = *reinterpret_cast<unsigned*>(&hh);
    l = *reinterpret_cast<unsigned*>(&ll);
}
__device__ __forceinline__ void mirror_write(int row, int col, float v) {
    __nv_bfloat16 hh = __float2bfloat16(v);
    d_poolh[(size_t)row * DIM + col] = hh;
    d_pooll[(size_t)row * DIM + col] = __float2bfloat16(v - __bfloat162float(hh));
}

#define LDM_X4(r, addr) \
    asm volatile("ldmatrix.sync.aligned.m8n8.x4.shared.b16 {%0,%1,%2,%3}, [%4];" \
        : "=r"((r)[0]), "=r"((r)[1]), "=r"((r)[2]), "=r"((r)[3]) : "r"(addr))
#define LDM_X4T(r, addr) \
    asm volatile("ldmatrix.sync.aligned.m8n8.x4.trans.shared.b16 {%0,%1,%2,%3}, [%4];" \
        : "=r"((r)[0]), "=r"((r)[1]), "=r"((r)[2]), "=r"((r)[3]) : "r"(addr))
#define MMA16816(d, a, b0, b1) \
    asm volatile("mma.sync.aligned.m16n8k16.row.col.f32.bf16.bf16.f32 " \
        "{%0,%1,%2,%3},{%4,%5,%6,%7},{%8,%9},{%0,%1,%2,%3};" \
        : "+f"((d)[0]), "+f"((d)[1]), "+f"((d)[2]), "+f"((d)[3]) \
        : "r"((a)[0]), "r"((a)[1]), "r"((a)[2]), "r"((a)[3]), "r"(b0), "r"(b1))
#define CPA16(dst, src) \
    asm volatile("cp.async.cg.shared.global [%0], [%1], 16;" :: "r"(dst), "l"(src) : "memory")
#define CPA_COMMIT() asm volatile("cp.async.commit_group;" ::: "memory")
#define CPA_WAIT()   asm volatile("cp.async.wait_group 0;" ::: "memory")

// ---------------- pipelined mma GEMM job: 64 rows x 64 cols x K256 ----------------
// amode 0: A rows from bf16 pool mirrors via dsc[seg=ks]; amode 1: A = gelu(i1_0+i1_1+gb).
// bpre: chunk-0 B tiles already cp.async'd into buffer 0 (group committed pre-barrier).
__device__ void gemm_mma(int amode, int ri, int ks, int bpre,
                         const int* __restrict__ dsc,
                         const float* __restrict__ gb,
                         const __nv_bfloat16* __restrict__ bH,
                         const __nv_bfloat16* __restrict__ bL, int Nw, int coloff,
                         float* __restrict__ C, int ldc,
                         char* dsb, unsigned sbase) {
    int tid = threadIdx.x;
    int lane = tid & 31, w = tid >> 5;
    int mrow0 = (w >> 2) * 16, ncol0 = (w & 3) * 16;
    float acc[8];
    #pragma unroll
    for (int i = 0; i < 8; i++) acc[i] = 0.f;

    int r = tid >> 3;            // 0..63
    int e8 = (tid & 7) * 8;      // 0..56
    int m = ri * 64 + r;
    unsigned stOff = (unsigned)(r * 72 + e8) * 2;
    unsigned aOff = ((mrow0 + (lane & 15)) * 72 + (lane >> 4) * 8) * 2;
    unsigned bOff = ((lane & 15) * 72 + ncol0 + (lane >> 4) * 8) * 2;

    int id = 0;
    if (amode == 0) {
        id = dsc[m * 3 + ks];
        if (id == -1) id = NPOOL;   // START mirror row
    }

    // A chunk loader: produces {hi uint4, lo uint4} (8 bf16 each)
    uint4 RA[2];
    auto loadA = [&](int c, uint4* R) {
        if (amode == 0) {
            if (id >= 0) {
                int colb = c * 64 + e8;
                R[0] = *(const uint4*)(d_poolh + (size_t)id * 256 + colb);
                R[1] = *(const uint4*)(d_pooll + (size_t)id * 256 + colb);
            } else {
                R[0] = make_uint4(0, 0, 0, 0);
                R[1] = make_uint4(0, 0, 0, 0);
            }
        } else {
            int kt = ks * 256 + c * 64 + e8;
            const float* pa = d_i1 + (size_t)m * 1024 + kt;
            float4 a0 = *(const float4*)pa,            a1 = *(const float4*)(pa + 4);
            float4 b0 = *(const float4*)(pa + 131072), b1 = *(const float4*)(pa + 131072 + 4);
            float4 g0 = *(const float4*)(gb + kt),     g1 = *(const float4*)(gb + kt + 4);
            float x0 = geluf(a0.x + b0.x + g0.x), x1 = geluf(a0.y + b0.y + g0.y);
            float x2 = geluf(a0.z + b0.z + g0.z), x3 = geluf(a0.w + b0.w + g0.w);
            float x4 = geluf(a1.x + b1.x + g1.x), x5 = geluf(a1.y + b1.y + g1.y);
            float x6 = geluf(a1.z + b1.z + g1.z), x7 = geluf(a1.w + b1.w + g1.w);
            uint4 H, L;
            cvt2(x0, x1, H.x, L.x); cvt2(x2, x3, H.y, L.y);
            cvt2(x4, x5, H.z, L.z); cvt2(x6, x7, H.w, L.w);
            R[0] = H; R[1] = L;
        }
    };
    auto storeA = [&](const uint4* R, int b) {
        *(uint4*)(dsb + OAH(b) + stOff) = R[0];
        *(uint4*)(dsb + OAL(b) + stOff) = R[1];
    };
    auto cpB = [&](int c, int b) {
        int kt = ks * 256 + c * 64 + r;
        size_t so = (size_t)kt * Nw + coloff + e8;
        CPA16(sbase + OBH(b) + stOff, bH + so);
        CPA16(sbase + OBL(b) + stOff, bL + so);
    };

    // prologue: chunk 0 into buffer 0 (B possibly prefetched pre-barrier)
    loadA(0, RA);
    if (!bpre) {
        cpB(0, 0);
        CPA_COMMIT();
    }
    storeA(RA, 0);
    CPA_WAIT();
    __syncthreads();

    int p = 0;
    for (int c = 0; c < 4; c++) {
        uint4 RN[2];
        if (c < 3) {
            loadA(c + 1, RN);
            cpB(c + 1, p ^ 1);
            CPA_COMMIT();
        }
        unsigned aH = sbase + OAH(p) + aOff;
        unsigned aL = sbase + OAL(p) + aOff;
        unsigned bHs = sbase + OBH(p) + bOff;
        unsigned bLs = sbase + OBL(p) + bOff;
        #pragma unroll
        for (int kk = 0; kk < 4; kk++) {
            unsigned ah[4], al[4], bh[4], bl[4];
            LDM_X4(ah, aH + kk * 32);
            LDM_X4(al, aL + kk * 32);
            LDM_X4T(bh, bHs + kk * 2304);
            LDM_X4T(bl, bLs + kk * 2304);
            MMA16816(acc,     ah, bh[0], bh[1]);
            MMA16816(acc,     al, bh[0], bh[1]);
            MMA16816(acc,     ah, bl[0], bl[1]);
            MMA16816(acc + 4, ah, bh[2], bh[3]);
            MMA16816(acc + 4, al, bh[2], bh[3]);
            MMA16816(acc + 4, ah, bl[2], bl[3]);
        }
        if (c < 3) {
            storeA(RN, p ^ 1);
            CPA_WAIT();
        }
        __syncthreads();
        p ^= 1;
    }

    int rw = mrow0 + (lane >> 2);
    int cw = ncol0 + (lane & 3) * 2;
    *(float2*)(C + (size_t)rw * ldc + cw)           = make_float2(acc[0], acc[1]);
    *(float2*)(C + (size_t)(rw + 8) * ldc + cw)     = make_float2(acc[2], acc[3]);
    *(float2*)(C + (size_t)rw * ldc + cw + 8)       = make_float2(acc[4], acc[5]);
    *(float2*)(C + (size_t)(rw + 8) * ldc + cw + 8) = make_float2(acc[6], acc[7]);
}

// ---------------- the persistent mega kernel ----------------
__global__ void __launch_bounds__(NT, 1)
mega(const float* __restrict__ sequence, const float* __restrict__ input_mask,
     const float* __restrict__ w_init, const float* __restrict__ b_init,
     const float* __restrict__ ln1_g, const float* __restrict__ ln1_b,
     const float* __restrict__ scorer_w, const float* __restrict__ scorer_b,
     const float* __restrict__ conv_w, const float* __restrict__ conv_b,
     const float* __restrict__ start,
     const float* __restrict__ wcell1_w, const float* __restrict__ wcell1_b,
     const float* __restrict__ wcell2_w, const float* __restrict__ wcell2_b,
     const float* __restrict__ ln2_g, const float* __restrict__ ln2_b,
     float* __restrict__ out) {
    extern __shared__ char dsb[];
    unsigned sbase = smem_u32(dsb);
    __shared__ float sred[16];
    __shared__ int   sparK[BEAMW], swrpos[BEAMW], swrval[BEAMW];

    int tid = threadIdx.x;
    int bid = blockIdx.x;
    int h   = tid >> 8;
    int col = tid & 255;
    unsigned ep = g_epbase + 1;

    // B prefetch for next phase's job (chunk 0 -> buffer 0), issued pre-barrier
    int pr = tid >> 3, pe8 = (tid & 7) * 8;
    unsigned pst = (unsigned)(pr * 72 + pe8) * 2;
    auto prefB = [&](const __nv_bfloat16* bH, const __nv_bfloat16* bL,
                     int Nw, int coloff, int ks) {
        size_t so = (size_t)(ks * 256 + pr) * Nw + coloff + pe8;
        CPA16(sbase + OBH(0) + pst, bH + so);
        CPA16(sbase + OBL(0) + pst, bL + so);
        CPA_COMMIT();
    };
    auto prefP1 = [&]() {
        if (bid < 64) {
            int ks = bid & 1, ct = (bid >> 1) & 15;
            prefB(d_w1h, d_w1l, 1024, ct * 64, ks);
        } else if (bid < 88) {
            int j = bid - 64;
            int ks = j % 3, ct = (j / 3) & 3;
            prefB(d_wch, d_wcl, 256, ct * 64, ks);
        }
    };
    auto prefP2 = [&]() {
        int ks = bid & 3, ct = (bid >> 2) & 15;
        prefB(d_w2h, d_w2l, 1024, ct * 64, ks);
    };

    // ---- init 0: weight conversion to bf16 hi/lo ----
    {
        const int T1 = 512 * 1024, T2 = T1 + 1024 * 1024, T3 = T2 + 768 * 256;
        for (int idx = bid * NT + tid; idx < T3; idx += G * NT) {
            float v; __nv_bfloat16* ph; __nv_bfloat16* pl; int o;
            if (idx < T1)      { v = wcell1_w[idx];      ph = d_w1h; pl = d_w1l; o = idx; }
            else if (idx < T2) { o = idx - T1; v = wcell2_w[o]; ph = d_w2h; pl = d_w2l; }
            else               { o = idx - T2; v = conv_w[o];   ph = d_wch; pl = d_wcl; }
            __nv_bfloat16 hh = __float2bfloat16(v);
            ph[o] = hh;
            pl[o] = __float2bfloat16(v - __bfloat162float(hh));
        }
    }
    // ---- init 1: LN1 tokens -> pool + mirrors; START mirror; zero descriptors ----
    {
        float* sX = (float*)dsb;
        for (int job = bid; job < (NB * SL) / 2; job += G) {
            int row = job * 2 + h;
            sX[h * 256 + col] = sequence[(size_t)row * DIM + col];
            __syncthreads();
            float acc = 0.f;
            for (int i = 0; i < DIM; i++)
                acc += sX[h * 256 + i] * w_init[i * DIM + col];
            float y = acc + b_init[col];
            float s1 = halfReduceSum(y, sred);
            float s2 = halfReduceSum(y * y, sred);
            float m = s1 * (1.0f / DIM);
            float var = s2 * (1.0f / DIM) - m * m;
            float v = (y - m) * rsqrtf(var + LNEPS) * ln1_g[col] + ln1_b[col];
            d_pool[(size_t)row * DIM + col] = v;
            mirror_write(row, col, v);
            __syncthreads();
        }
        if (bid == G - 1 && tid < 768) { d_asrc[0][tid] = 0; d_asrc[1][tid] = 0; }
        if (bid == 0 && tid < 256) mirror_write(NPOOL, tid, start[tid]);
    }
    gbar(ep);

    // ---- init 2: stack tables + first descriptors (K=1) ----
    if (bid < NB && tid == 0) {
        int n = bid;
        d_tab[0][n * BEAMW][0] = n * SL + 0;
        d_tab[0][n * BEAMW][1] = n * SL + 1;
        int p = (input_mask[n * SL + 1] > 0.5f) ? 1 : 0;
        d_p[0][n * BEAMW] = p;
        d_q[0][n * BEAMW] = 0;
        d_asrc[0][n * 3 + 0] = (p >= 1) ? (n * SL + 0) : -1;
        d_asrc[0][n * 3 + 1] = n * SL + p;
        d_asrc[0][n * 3 + 2] = n * SL + 2;
    }
    prefP1();
    gbar(ep);

    int K = 1, buf = 0;
    for (int t = 2; t <= 2 * SL - 2; t++) {
        int newK = (2 * K < BEAMW) ? 2 * K : BEAMW;
        int nb2 = buf ^ 1;
        const int* dsc = d_asrc[buf];

        // ---- P1: cell1 (ks2: 64 jobs) + conv (ks3: 24 jobs) ----
        if (bid < 88) {
            if (bid < 64) {
                int ks = bid & 1, ct = (bid >> 1) & 15, ri = bid >> 5;
                gemm_mma(0, ri, ks, 1, dsc, nullptr,
                         d_w1h, d_w1l, 1024, ct * 64,
                         d_i1 + (size_t)ks * 131072 + (size_t)ri * 64 * 1024 + ct * 64,
                         1024, dsb, sbase);
            } else {
                int j = bid - 64;
                int ks = j % 3, r2 = j / 3;
                int ct = r2 & 3, ri = r2 >> 2;
                gemm_mma(0, ri, ks, 1, dsc, nullptr,
                         d_wch, d_wcl, 256, ct * 64,
                         d_cpart + (size_t)ks * 32768 + (size_t)ri * 64 * 256 + ct * 64,
                         256, dsb, sbase);
            }
        }
        prefP2();
        gbar(ep);

        // ---- P2: cell2 (ks4: 128 jobs) + distributed scores tail ----
        {
            int ks = bid & 3, ct = (bid >> 2) & 15, ri = bid >> 6;
            gemm_mma(1, ri, ks, 1, nullptr, wcell1_b,
                     d_w2h, d_w2l, 1024, ct * 64,
                     d_c2 + (size_t)ks * 131072 + (size_t)ri * 64 * 1024 + ct * 64,
                     1024, dsb, sbase);
        }
        if (bid < 64) {
            int m = 2 * bid + h;
            int valid = (m < NB * K);
            int mm = valid ? m : 0;
            float s = d_cpart[mm * 256 + col]
                    + d_cpart[32768 + mm * 256 + col]
                    + d_cpart[65536 + mm * 256 + col];
            float y = valid ? geluf(s + conv_b[col]) * scorer_w[col] : 0.f;
            float dot = halfReduceSum(y, sred);
            if (col == 0 && valid) {
                int n = mm / K, k = mm % K;
                float dec = sigmoidf_(dot + scorer_b[0]);
                int p = d_p[buf][n * BEAMW + k];
                int q = d_q[buf][n * BEAMW + k];
                float lp  = (p >= 1) ? 1.0f : 0.0f;
                float cmf = (q < SL - 2) ? input_mask[n * SL + 2 + q] : 0.0f;
                float bz  = ((lp == 0.0f) && (cmf == 0.0f)) ? 1.0f : 0.0f;
                float rs = cmf * dec + (1.0f - cmf);
                rs = lp * rs; rs = bz + (1.0f - bz) * rs; rs = logf(rs + EPSC);
                float ss = lp * (1.0f - dec) + (1.0f - lp);
                ss = cmf * ss; ss = (1.0f - bz) * ss; ss = logf(ss + EPSC);
                d_rs[mm] = rs;
                d_ss[mm] = ss;
            }
        }
        gbar(ep);

        // ---- P3: top-k + tables + descriptors (blocks 0-31) || compose (0-63) ----
        if (bid < NB) {
            int n = bid;
            if (tid == 0) {
                int C2 = 2 * K;
                float sc[8];
                for (int c = 0; c < C2; c++)
                    sc[c] = (c < K) ? d_rs[n * K + c] : d_ss[n * K + (c - K)];
                int sel[BEAMW];
                if (C2 <= BEAMW) {
                    for (int s2 = 0; s2 < C2; s2++) { sel[s2] = s2; d_bscore[n * BEAMW + s2] = sc[s2]; }
                } else {
                    bool used[8];
                    for (int c = 0; c < C2; c++) used[c] = false;
                    for (int s2 = 0; s2 < BEAMW; s2++) {
                        int best = -1; float bv = 0.f;
                        for (int c = 0; c < C2; c++) {
                            if (used[c]) continue;
                            if (best < 0 || sc[c] > bv) { best = c; bv = sc[c]; }
                        }
                        used[best] = true; sel[s2] = best;
                        d_bscore[n * BEAMW + s2] = bv;
                    }
                }
                for (int s2 = 0; s2 < newK; s2++) {
                    int c = sel[s2];
                    int isred = (c < K);
                    int k = isred ? c : (c - K);
                    int p = d_p[buf][n * BEAMW + k];
                    int q = d_q[buf][n * BEAMW + k];
                    int lp = (p >= 1);
                    float cmf = (q < SL - 2) ? input_mask[n * SL + 2 + q] : 0.0f;
                    int cm = (cmf > 0.5f);
                    int wr_pos = -1, newp = p, newq = q, wr_val = 0;
                    if (isred) {
                        if (lp) { wr_pos = p - 1; newp = p - 1;
                                  wr_val = NB * SL + (t - 2) * (NB * BEAMW) + n * BEAMW + k; }
                    } else {
                        newq = q + 1;
                        if (cm) { wr_pos = p + 1; newp = p + 1; wr_val = n * SL + 2 + q; }
                    }
                    sparK[s2] = k; swrpos[s2] = wr_pos; swrval[s2] = wr_val;
                    d_p[nb2][n * BEAMW + s2] = newp;
                    d_q[nb2][n * BEAMW + s2] = newq;
                    const int* ot = d_tab[buf][n * BEAMW + k];
                    int laster = -1;
                    if (newp >= 1) {
                        int d = newp - 1;
                        laster = (d == wr_pos) ? wr_val : ot[d];
                    }
                    int lastv = (newp == wr_pos) ? wr_val : ot[newp];
                    int curv  = (newq < SL - 2) ? (n * SL + 2 + newq) : -2;
                    int m2 = n * newK + s2;
                    d_asrc[nb2][m2 * 3 + 0] = laster;
                    d_asrc[nb2][m2 * 3 + 1] = lastv;
                    d_asrc[nb2][m2 * 3 + 2] = curv;
                }
            }
            __syncthreads();
            if (tid < newK * SL) {
                int s2 = tid / SL, d = tid % SL;
                int pk = sparK[s2];
                int v = d_tab[buf][n * BEAMW + pk][d];
                if (d == swrpos[s2]) v = swrval[s2];
                d_tab[nb2][n * BEAMW + s2][d] = v;
            }
            __syncthreads();
        }
        if (bid < 64) {
            int m = 2 * bid + h;
            int valid = (m < NB * K);
            int mm = valid ? m : 0;
            const float* c0 = d_c2 + (size_t)mm * 1024;
            float seg[4];
            #pragma unroll
            for (int sg = 0; sg < 4; sg++) {
                seg[sg] = c0[sg * 256 + col]
                        + c0[131072 + sg * 256 + col]
                        + c0[262144 + sg * 256 + col]
                        + c0[393216 + sg * 256 + col]
                        + wcell2_b[sg * 256 + col];
            }
            int id1 = dsc[mm * 3 + 0];
            int id2 = dsc[mm * 3 + 1];
            float c1 = (id1 >= 0) ? d_pool[(size_t)id1 * DIM + col] : start[col];
            float c2v = d_pool[(size_t)id2 * DIM + col];
            float x = sigmoidf_(seg[0]) * c1
                    + sigmoidf_(seg[1]) * c2v
                    + sigmoidf_(seg[2]) * seg[3];
            float xm = valid ? x : 0.f;
            float s1 = halfReduceSum(xm, sred);
            float s2 = halfReduceSum(xm * xm, sred);
            if (valid) {
                float mn = s1 * (1.0f / DIM);
                float var = s2 * (1.0f / DIM) - mn * mn;
                int n = mm / K, k = mm % K;
                int rid = NB * SL + (t - 2) * (NB * BEAMW) + n * BEAMW + k;
                float v = (x - mn) * rsqrtf(var + LNEPS) * ln2_g[col] + ln2_b[col];
                d_pool[(size_t)rid * DIM + col] = v;
                mirror_write(rid, col, v);
            }
        }
        if (t < 2 * SL - 2) prefP1();
        gbar(ep);
        buf ^= 1;
        K = newK;
    }

    // ---- final: softmax over beam scores, weighted top-of-stack sum ----
    if (bid < NB && h == 0) {
        int n = bid;
        float sc[BEAMW];
        float mx = -1e30f;
        #pragma unroll
        for (int k = 0; k < BEAMW; k++) { sc[k] = d_bscore[n * BEAMW + k]; mx = fmaxf(mx, sc[k]); }
        float e[BEAMW], sum = 0.f;
        #pragma unroll
        for (int k = 0; k < BEAMW; k++) { e[k] = expf(sc[k] - mx); sum += e[k]; }
        float o = 0.f;
        #pragma unroll
        for (int k = 0; k < BEAMW; k++) {
            int p = d_p[buf][n * BEAMW + k];
            int slot = d_tab[buf][n * BEAMW + k][p];
            o += (e[k] / sum) * d_pool[(size_t)slot * DIM + col];
        }
        out[(size_t)n * DIM + col] = o;
    }
    if (bid == 0 && tid == 0) g_epbase = ep - 1;
}

// ---------------- host launcher ----------------
extern "C" void kernel_launch(void* const* d_in, const int* in_sizes, int n_in,
                              void* d_out, int out_size) {
    const float* sequence   = (const float*)d_in[0];
    const float* input_mask = (const float*)d_in[1];
    const float* w_init     = (const float*)d_in[2];
    const float* b_init     = (const float*)d_in[3];
    const float* ln1_g      = (const float*)d_in[4];
    const float* ln1_b      = (const float*)d_in[5];
    const float* scorer_w   = (const float*)d_in[6];
    const float* scorer_b   = (const float*)d_in[7];
    const float* conv_w     = (const float*)d_in[8];
    const float* conv_b     = (const float*)d_in[9];
    const float* start      = (const float*)d_in[10];
    const float* wcell1_w   = (const float*)d_in[11];
    const float* wcell1_b   = (const float*)d_in[12];
    const float* wcell2_w   = (const float*)d_in[13];
    const float* wcell2_b   = (const float*)d_in[14];
    const float* ln2_g      = (const float*)d_in[15];
    const float* ln2_b      = (const float*)d_in[16];
    float* out = (float*)d_out;

    cudaFuncSetAttribute(mega, cudaFuncAttributeMaxDynamicSharedMemorySize, SMEM_DYN);
    mega<<<G, NT, SMEM_DYN>>>(sequence, input_mask, w_init, b_init, ln1_g, ln1_b,
                              scorer_w, scorer_b, conv_w, conv_b, start,
                              wcell1_w, wcell1_b, wcell2_w, wcell2_b, ln2_g, ln2_b, out);
}

// round 17
// speedup vs baseline: 1.0171x; 1.0171x over previous
#include <cuda_runtime.h>
#include <cuda_bf16.h>
#include <math.h>

#define NB    32
#define SL    20
#define DIM   256
#define BEAMW 4
#define G     128
#define NT    512
#define EPSC  1e-8f
#define LNEPS 1e-5f
#define NPOOL (NB * SL + 37 * NB * BEAMW)

// dynamic smem: 8 buffers of 64*72 bf16 (9216 B): AH0 AH1 AL0 AL1 BH0 BH1 BL0 BL1
#define BUFB 9216
#define OAH(b) ((b) * BUFB)
#define OAL(b) (18432 + (b) * BUFB)
#define OBH(b) (36864 + (b) * BUFB)
#define OBL(b) (55296 + (b) * BUFB)
#define SMEM_DYN 73728

// ---------------- static device scratch ----------------
__device__ float d_pool[NPOOL * DIM];
__device__ int   d_tab[2][NB * BEAMW][SL];
__device__ int   d_p[2][NB * BEAMW];
__device__ int   d_q[2][NB * BEAMW];
__device__ int   d_asrc[2][128 * 3];       // laster/last/cur: >=0 pool row, -1 start, -2 zero
__device__ float d_cpart[3 * 128 * 256];   // conv partials ks3
__device__ float d_i1[2 * 128 * 1024];     // cell1 partials ks2
__device__ float d_c2[4 * 128 * 1024];     // cell2 partials ks4
__device__ float d_rs[128], d_ss[128];
__device__ float d_bscore[NB * BEAMW];
__device__ __nv_bfloat16 d_w1h[512 * 1024],  d_w1l[512 * 1024];
__device__ __nv_bfloat16 d_w2h[1024 * 1024], d_w2l[1024 * 1024];
__device__ __nv_bfloat16 d_wch[768 * 256],   d_wcl[768 * 256];
__device__ volatile unsigned g_flags[G];
__device__ volatile unsigned g_rel;
__device__ unsigned g_epbase = 0;          // persists across graph replays

// ---------------- flag-array grid barrier (replay-safe epochs) ----------------
// arrival: per-block own-word store; detection: block 0 (128 pollers, 1 flag each);
// release: single word. Epochs are monotonic across graph replays via g_epbase.
__device__ __forceinline__ void gbar(unsigned& ep) {
    __syncthreads();
    int tid = threadIdx.x;
    int bid = blockIdx.x;
    if (tid == 0) {
        __threadfence();
        g_flags[bid] = ep;
    }
    if (bid == 0) {
        if (tid < G) {
            while (g_flags[tid] < ep) { }
        }
        __syncthreads();
        if (tid == 0) {
            __threadfence();
            g_rel = ep;
        }
    } else {
        if (tid == 0) {
            while (g_rel < ep) { }
            __threadfence();
        }
    }
    __syncthreads();
    ep++;
}

// ---------------- helpers ----------------
__device__ __forceinline__ float geluf(float x) {
    return 0.5f * x * (1.0f + erff(x * 0.7071067811865476f));
}
__device__ __forceinline__ float sigmoidf_(float x) {
    return 1.0f / (1.0f + expf(-x));
}
__device__ __forceinline__ float halfReduceSum(float v, float* sbuf) {
    int tid = threadIdx.x;
    #pragma unroll
    for (int o = 16; o > 0; o >>= 1) v += __shfl_down_sync(0xffffffffu, v, o);
    if ((tid & 31) == 0) sbuf[tid >> 5] = v;
    __syncthreads();
    int h = tid >> 8;
    float r = 0.f;
    #pragma unroll
    for (int w = 0; w < 8; w++) r += sbuf[h * 8 + w];
    __syncthreads();
    return r;
}
__device__ __forceinline__ unsigned smem_u32(const void* p) {
    unsigned a;
    asm("{ .reg .u64 t; cvta.to.shared.u64 t, %1; cvt.u32.u64 %0, t; }" : "=r"(a) : "l"(p));
    return a;
}
__device__ __forceinline__ void cvt2(float a, float b, unsigned& h, unsigned& l) {
    __nv_bfloat162 hh = __floats2bfloat162_rn(a, b);
    __nv_bfloat162 ll = __floats2bfloat162_rn(a - __bfloat162float(hh.x),
                                              b - __bfloat162float(hh.y));
    h = *reinterpret_cast<unsigned*>(&hh);
    l = *reinterpret_cast<unsigned*>(&ll);
}

#define LDM_X4(r, addr) \
    asm volatile("ldmatrix.sync.aligned.m8n8.x4.shared.b16 {%0,%1,%2,%3}, [%4];" \
        : "=r"((r)[0]), "=r"((r)[1]), "=r"((r)[2]), "=r"((r)[3]) : "r"(addr))
#define LDM_X4T(r, addr) \
    asm volatile("ldmatrix.sync.aligned.m8n8.x4.trans.shared.b16 {%0,%1,%2,%3}, [%4];" \
        : "=r"((r)[0]), "=r"((r)[1]), "=r"((r)[2]), "=r"((r)[3]) : "r"(addr))
#define MMA16816(d, a, b0, b1) \
    asm volatile("mma.sync.aligned.m16n8k16.row.col.f32.bf16.bf16.f32 " \
        "{%0,%1,%2,%3},{%4,%5,%6,%7},{%8,%9},{%0,%1,%2,%3};" \
        : "+f"((d)[0]), "+f"((d)[1]), "+f"((d)[2]), "+f"((d)[3]) \
        : "r"((a)[0]), "r"((a)[1]), "r"((a)[2]), "r"((a)[3]), "r"(b0), "r"(b1))
#define CPA16(dst, src) \
    asm volatile("cp.async.cg.shared.global [%0], [%1], 16;" :: "r"(dst), "l"(src) : "memory")
#define CPA_COMMIT() asm volatile("cp.async.commit_group;" ::: "memory")
#define CPA_WAIT()   asm volatile("cp.async.wait_group 0;" ::: "memory")

// ---------------- pipelined mma GEMM job: 64 rows x 64 cols x K256 ----------------
// amode 0: A rows from pool via dsc[seg=ks]; amode 1: A = gelu(i1_0+i1_1+gb).
__device__ void gemm_mma(int amode, int ri, int ks,
                         const int* __restrict__ dsc, const float* __restrict__ start,
                         const float* __restrict__ gb,
                         const __nv_bfloat16* __restrict__ bH,
                         const __nv_bfloat16* __restrict__ bL, int Nw, int coloff,
                         float* __restrict__ C, int ldc,
                         char* dsb, unsigned sbase) {
    int tid = threadIdx.x;
    int lane = tid & 31, w = tid >> 5;
    int mrow0 = (w >> 2) * 16, ncol0 = (w & 3) * 16;
    float acc[8];
    #pragma unroll
    for (int i = 0; i < 8; i++) acc[i] = 0.f;

    int r = tid >> 3;            // 0..63
    int e8 = (tid & 7) * 8;      // 0..56
    int m = ri * 64 + r;
    unsigned stOff = (unsigned)(r * 72 + e8) * 2;
    unsigned aOff = ((mrow0 + (lane & 15)) * 72 + (lane >> 4) * 8) * 2;
    unsigned bOff = ((lane & 15) * 72 + ncol0 + (lane >> 4) * 8) * 2;

    int id = 0;
    if (amode == 0) id = dsc[m * 3 + ks];

    float x[8];
    auto loadA = [&](int c, float* xr) {
        if (amode == 0) {
            int colb = c * 64 + e8;
            if (id >= 0) {
                const float* s = d_pool + (size_t)id * 256 + colb;
                float4 v0 = *(const float4*)s, v1 = *(const float4*)(s + 4);
                xr[0] = v0.x; xr[1] = v0.y; xr[2] = v0.z; xr[3] = v0.w;
                xr[4] = v1.x; xr[5] = v1.y; xr[6] = v1.z; xr[7] = v1.w;
            } else if (id == -1) {
                const float* s = start + c * 64 + e8;
                float4 v0 = *(const float4*)s, v1 = *(const float4*)(s + 4);
                xr[0] = v0.x; xr[1] = v0.y; xr[2] = v0.z; xr[3] = v0.w;
                xr[4] = v1.x; xr[5] = v1.y; xr[6] = v1.z; xr[7] = v1.w;
            } else {
                #pragma unroll
                for (int j = 0; j < 8; j++) xr[j] = 0.f;
            }
        } else {
            int kt = ks * 256 + c * 64 + e8;
            const float* pa = d_i1 + (size_t)m * 1024 + kt;
            float4 a0 = *(const float4*)pa,            a1 = *(const float4*)(pa + 4);
            float4 b0 = *(const float4*)(pa + 131072), b1 = *(const float4*)(pa + 131072 + 4);
            float4 g0 = *(const float4*)(gb + kt),     g1 = *(const float4*)(gb + kt + 4);
            xr[0] = geluf(a0.x + b0.x + g0.x); xr[1] = geluf(a0.y + b0.y + g0.y);
            xr[2] = geluf(a0.z + b0.z + g0.z); xr[3] = geluf(a0.w + b0.w + g0.w);
            xr[4] = geluf(a1.x + b1.x + g1.x); xr[5] = geluf(a1.y + b1.y + g1.y);
            xr[6] = geluf(a1.z + b1.z + g1.z); xr[7] = geluf(a1.w + b1.w + g1.w);
        }
    };
    auto storeA = [&](const float* xr, int b) {
        uint4 H, L;
        cvt2(xr[0], xr[1], H.x, L.x); cvt2(xr[2], xr[3], H.y, L.y);
        cvt2(xr[4], xr[5], H.z, L.z); cvt2(xr[6], xr[7], H.w, L.w);
        *(uint4*)(dsb + OAH(b) + stOff) = H;
        *(uint4*)(dsb + OAL(b) + stOff) = L;
    };
    auto cpB = [&](int c, int b) {
        int kt = ks * 256 + c * 64 + r;
        size_t so = (size_t)kt * Nw + coloff + e8;
        CPA16(sbase + OBH(b) + stOff, bH + so);
        CPA16(sbase + OBL(b) + stOff, bL + so);
    };

    loadA(0, x);
    cpB(0, 0);
    CPA_COMMIT();
    storeA(x, 0);
    CPA_WAIT();
    __syncthreads();

    int p = 0;
    for (int c = 0; c < 4; c++) {
        float xn[8];
        if (c < 3) {
            loadA(c + 1, xn);
            cpB(c + 1, p ^ 1);
            CPA_COMMIT();
        }
        unsigned aH = sbase + OAH(p) + aOff;
        unsigned aL = sbase + OAL(p) + aOff;
        unsigned bHs = sbase + OBH(p) + bOff;
        unsigned bLs = sbase + OBL(p) + bOff;
        #pragma unroll
        for (int kk = 0; kk < 4; kk++) {
            unsigned ah[4], al[4], bh[4], bl[4];
            LDM_X4(ah, aH + kk * 32);
            LDM_X4(al, aL + kk * 32);
            LDM_X4T(bh, bHs + kk * 2304);
            LDM_X4T(bl, bLs + kk * 2304);
            MMA16816(acc,     ah, bh[0], bh[1]);
            MMA16816(acc,     al, bh[0], bh[1]);
            MMA16816(acc,     ah, bl[0], bl[1]);
            MMA16816(acc + 4, ah, bh[2], bh[3]);
            MMA16816(acc + 4, al, bh[2], bh[3]);
            MMA16816(acc + 4, ah, bl[2], bl[3]);
        }
        if (c < 3) {
            storeA(xn, p ^ 1);
            CPA_WAIT();
        }
        __syncthreads();
        p ^= 1;
    }

    int rw = mrow0 + (lane >> 2);
    int cw = ncol0 + (lane & 3) * 2;
    *(float2*)(C + (size_t)rw * ldc + cw)           = make_float2(acc[0], acc[1]);
    *(float2*)(C + (size_t)(rw + 8) * ldc + cw)     = make_float2(acc[2], acc[3]);
    *(float2*)(C + (size_t)rw * ldc + cw + 8)       = make_float2(acc[4], acc[5]);
    *(float2*)(C + (size_t)(rw + 8) * ldc + cw + 8) = make_float2(acc[6], acc[7]);
}

// ---------------- the persistent mega kernel ----------------
__global__ void __launch_bounds__(NT, 1)
mega(const float* __restrict__ sequence, const float* __restrict__ input_mask,
     const float* __restrict__ w_init, const float* __restrict__ b_init,
     const float* __restrict__ ln1_g, const float* __restrict__ ln1_b,
     const float* __restrict__ scorer_w, const float* __restrict__ scorer_b,
     const float* __restrict__ conv_w, const float* __restrict__ conv_b,
     const float* __restrict__ start,
     const float* __restrict__ wcell1_w, const float* __restrict__ wcell1_b,
     const float* __restrict__ wcell2_w, const float* __restrict__ wcell2_b,
     const float* __restrict__ ln2_g, const float* __restrict__ ln2_b,
     float* __restrict__ out) {
    extern __shared__ char dsb[];
    unsigned sbase = smem_u32(dsb);
    __shared__ float sred[16];
    __shared__ int   sparK[BEAMW], swrpos[BEAMW], swrval[BEAMW];

    int tid = threadIdx.x;
    int bid = blockIdx.x;
    int h   = tid >> 8;
    int col = tid & 255;
    unsigned ep = g_epbase + 1;

    // ---- init 0: elementwise weight conversion to bf16 hi/lo ----
    {
        const int T1 = 512 * 1024, T2 = T1 + 1024 * 1024, T3 = T2 + 768 * 256;
        for (int idx = bid * NT + tid; idx < T3; idx += G * NT) {
            float v; __nv_bfloat16* ph; __nv_bfloat16* pl; int o;
            if (idx < T1)      { v = wcell1_w[idx];      ph = d_w1h; pl = d_w1l; o = idx; }
            else if (idx < T2) { o = idx - T1; v = wcell2_w[o]; ph = d_w2h; pl = d_w2l; }
            else               { o = idx - T2; v = conv_w[o];   ph = d_wch; pl = d_wcl; }
            __nv_bfloat16 hh = __float2bfloat16(v);
            ph[o] = hh;
            pl[o] = __float2bfloat16(v - __bfloat162float(hh));
        }
    }
    // ---- init 1: pool tokens = LN1(sequence @ w_init + b_init); 2 rows/block ----
    {
        float* sX = (float*)dsb;
        for (int job = bid; job < (NB * SL) / 2; job += G) {
            int row = job * 2 + h;
            sX[h * 256 + col] = sequence[(size_t)row * DIM + col];
            __syncthreads();
            float acc = 0.f;
            for (int i = 0; i < DIM; i++)
                acc += sX[h * 256 + i] * w_init[i * DIM + col];
            float y = acc + b_init[col];
            float s1 = halfReduceSum(y, sred);
            float s2 = halfReduceSum(y * y, sred);
            float m = s1 * (1.0f / DIM);
            float var = s2 * (1.0f / DIM) - m * m;
            d_pool[(size_t)row * DIM + col] =
                (y - m) * rsqrtf(var + LNEPS) * ln1_g[col] + ln1_b[col];
            __syncthreads();
        }
        if (bid == G - 1 && tid < 768) { d_asrc[0][tid] = 0; d_asrc[1][tid] = 0; }
    }
    gbar(ep);

    // ---- init 2: stack tables + first descriptors (K=1) ----
    if (bid < NB && tid == 0) {
        int n = bid;
        d_tab[0][n * BEAMW][0] = n * SL + 0;
        d_tab[0][n * BEAMW][1] = n * SL + 1;
        int p = (input_mask[n * SL + 1] > 0.5f) ? 1 : 0;
        d_p[0][n * BEAMW] = p;
        d_q[0][n * BEAMW] = 0;
        d_asrc[0][n * 3 + 0] = (p >= 1) ? (n * SL + 0) : -1;
        d_asrc[0][n * 3 + 1] = n * SL + p;
        d_asrc[0][n * 3 + 2] = n * SL + 2;
    }
    gbar(ep);

    int K = 1, buf = 0;
    for (int t = 2; t <= 2 * SL - 2; t++) {
        int newK = (2 * K < BEAMW) ? 2 * K : BEAMW;
        int nb2 = buf ^ 1;
        const int* dsc = d_asrc[buf];

        // ---- P1: cell1 (ks2: 64 jobs) + conv (ks3: 24 jobs) ----
        if (bid < 88) {
            if (bid < 64) {
                int ks = bid & 1, ct = (bid >> 1) & 15, ri = bid >> 5;
                gemm_mma(0, ri, ks, dsc, start, nullptr,
                         d_w1h, d_w1l, 1024, ct * 64,
                         d_i1 + (size_t)ks * 131072 + (size_t)ri * 64 * 1024 + ct * 64,
                         1024, dsb, sbase);
            } else {
                int j = bid - 64;
                int ks = j % 3, r2 = j / 3;
                int ct = r2 & 3, ri = r2 >> 2;
                gemm_mma(0, ri, ks, dsc, start, nullptr,
                         d_wch, d_wcl, 256, ct * 64,
                         d_cpart + (size_t)ks * 32768 + (size_t)ri * 64 * 256 + ct * 64,
                         256, dsb, sbase);
            }
        }
        gbar(ep);

        // ---- P2: cell2 (ks4: 128 jobs) + distributed scores tail ----
        {
            int ks = bid & 3, ct = (bid >> 2) & 15, ri = bid >> 6;
            gemm_mma(1, ri, ks, nullptr, nullptr, wcell1_b,
                     d_w2h, d_w2l, 1024, ct * 64,
                     d_c2 + (size_t)ks * 131072 + (size_t)ri * 64 * 1024 + ct * 64,
                     1024, dsb, sbase);
        }
        if (bid < 64) {
            int m = 2 * bid + h;
            int valid = (m < NB * K);
            int mm = valid ? m : 0;
            float s = d_cpart[mm * 256 + col]
                    + d_cpart[32768 + mm * 256 + col]
                    + d_cpart[65536 + mm * 256 + col];
            float y = valid ? geluf(s + conv_b[col]) * scorer_w[col] : 0.f;
            float dot = halfReduceSum(y, sred);
            if (col == 0 && valid) {
                int n = mm / K, k = mm % K;
                float dec = sigmoidf_(dot + scorer_b[0]);
                int p = d_p[buf][n * BEAMW + k];
                int q = d_q[buf][n * BEAMW + k];
                float lp  = (p >= 1) ? 1.0f : 0.0f;
                float cmf = (q < SL - 2) ? input_mask[n * SL + 2 + q] : 0.0f;
                float bz  = ((lp == 0.0f) && (cmf == 0.0f)) ? 1.0f : 0.0f;
                float rs = cmf * dec + (1.0f - cmf);
                rs = lp * rs; rs = bz + (1.0f - bz) * rs; rs = logf(rs + EPSC);
                float ss = lp * (1.0f - dec) + (1.0f - lp);
                ss = cmf * ss; ss = (1.0f - bz) * ss; ss = logf(ss + EPSC);
                d_rs[mm] = rs;
                d_ss[mm] = ss;
            }
        }
        gbar(ep);

        // ---- P3: top-k + tables + descriptors (blocks 0-31) || compose (0-63) ----
        if (bid < NB) {
            int n = bid;
            if (tid == 0) {
                int C2 = 2 * K;
                float sc[8];
                for (int c = 0; c < C2; c++)
                    sc[c] = (c < K) ? d_rs[n * K + c] : d_ss[n * K + (c - K)];
                int sel[BEAMW];
                if (C2 <= BEAMW) {
                    for (int s2 = 0; s2 < C2; s2++) { sel[s2] = s2; d_bscore[n * BEAMW + s2] = sc[s2]; }
                } else {
                    bool used[8];
                    for (int c = 0; c < C2; c++) used[c] = false;
                    for (int s2 = 0; s2 < BEAMW; s2++) {
                        int best = -1; float bv = 0.f;
                        for (int c = 0; c < C2; c++) {
                            if (used[c]) continue;
                            if (best < 0 || sc[c] > bv) { best = c; bv = sc[c]; }
                        }
                        used[best] = true; sel[s2] = best;
                        d_bscore[n * BEAMW + s2] = bv;
                    }
                }
                for (int s2 = 0; s2 < newK; s2++) {
                    int c = sel[s2];
                    int isred = (c < K);
                    int k = isred ? c : (c - K);
                    int p = d_p[buf][n * BEAMW + k];
                    int q = d_q[buf][n * BEAMW + k];
                    int lp = (p >= 1);
                    float cmf = (q < SL - 2) ? input_mask[n * SL + 2 + q] : 0.0f;
                    int cm = (cmf > 0.5f);
                    int wr_pos = -1, newp = p, newq = q, wr_val = 0;
                    if (isred) {
                        if (lp) { wr_pos = p - 1; newp = p - 1;
                                  wr_val = NB * SL + (t - 2) * (NB * BEAMW) + n * BEAMW + k; }
                    } else {
                        newq = q + 1;
                        if (cm) { wr_pos = p + 1; newp = p + 1; wr_val = n * SL + 2 + q; }
                    }
                    sparK[s2] = k; swrpos[s2] = wr_pos; swrval[s2] = wr_val;
                    d_p[nb2][n * BEAMW + s2] = newp;
                    d_q[nb2][n * BEAMW + s2] = newq;
                    const int* ot = d_tab[buf][n * BEAMW + k];
                    int laster = -1;
                    if (newp >= 1) {
                        int d = newp - 1;
                        laster = (d == wr_pos) ? wr_val : ot[d];
                    }
                    int lastv = (newp == wr_pos) ? wr_val : ot[newp];
                    int curv  = (newq < SL - 2) ? (n * SL + 2 + newq) : -2;
                    int m2 = n * newK + s2;
                    d_asrc[nb2][m2 * 3 + 0] = laster;
                    d_asrc[nb2][m2 * 3 + 1] = lastv;
                    d_asrc[nb2][m2 * 3 + 2] = curv;
                }
            }
            __syncthreads();
            if (tid < newK * SL) {
                int s2 = tid / SL, d = tid % SL;
                int pk = sparK[s2];
                int v = d_tab[buf][n * BEAMW + pk][d];
                if (d == swrpos[s2]) v = swrval[s2];
                d_tab[nb2][n * BEAMW + s2][d] = v;
            }
            __syncthreads();
        }
        if (bid < 64) {
            int m = 2 * bid + h;
            int valid = (m < NB * K);
            int mm = valid ? m : 0;
            const float* c0 = d_c2 + (size_t)mm * 1024;
            float seg[4];
            #pragma unroll
            for (int sg = 0; sg < 4; sg++) {
                seg[sg] = c0[sg * 256 + col]
                        + c0[131072 + sg * 256 + col]
                        + c0[262144 + sg * 256 + col]
                        + c0[393216 + sg * 256 + col]
                        + wcell2_b[sg * 256 + col];
            }
            int id1 = dsc[mm * 3 + 0];
            int id2 = dsc[mm * 3 + 1];
            float c1 = (id1 >= 0) ? d_pool[(size_t)id1 * DIM + col] : start[col];
            float c2v = d_pool[(size_t)id2 * DIM + col];
            float x = sigmoidf_(seg[0]) * c1
                    + sigmoidf_(seg[1]) * c2v
                    + sigmoidf_(seg[2]) * seg[3];
            float xm = valid ? x : 0.f;
            float s1 = halfReduceSum(xm, sred);
            float s2 = halfReduceSum(xm * xm, sred);
            if (valid) {
                float mn = s1 * (1.0f / DIM);
                float var = s2 * (1.0f / DIM) - mn * mn;
                int n = mm / K, k = mm % K;
                int rid = NB * SL + (t - 2) * (NB * BEAMW) + n * BEAMW + k;
                d_pool[(size_t)rid * DIM + col] =
                    (x - mn) * rsqrtf(var + LNEPS) * ln2_g[col] + ln2_b[col];
            }
        }
        gbar(ep);
        buf ^= 1;
        K = newK;
    }

    // ---- final: softmax over beam scores, weighted top-of-stack sum ----
    if (bid < NB && h == 0) {
        int n = bid;
        float sc[BEAMW];
        float mx = -1e30f;
        #pragma unroll
        for (int k = 0; k < BEAMW; k++) { sc[k] = d_bscore[n * BEAMW + k]; mx = fmaxf(mx, sc[k]); }
        float e[BEAMW], sum = 0.f;
        #pragma unroll
        for (int k = 0; k < BEAMW; k++) { e[k] = expf(sc[k] - mx); sum += e[k]; }
        float o = 0.f;
        #pragma unroll
        for (int k = 0; k < BEAMW; k++) {
            int p = d_p[buf][n * BEAMW + k];
            int slot = d_tab[buf][n * BEAMW + k][p];
            o += (e[k] / sum) * d_pool[(size_t)slot * DIM + col];
        }
        out[(size_t)n * DIM + col] = o;
    }
    if (bid == 0 && tid == 0) g_epbase = ep - 1;
}

// ---------------- host launcher ----------------
extern "C" void kernel_launch(void* const* d_in, const int* in_sizes, int n_in,
                              void* d_out, int out_size) {
    const float* sequence   = (const float*)d_in[0];
    const float* input_mask = (const float*)d_in[1];
    const float* w_init     = (const float*)d_in[2];
    const float* b_init     = (const float*)d_in[3];
    const float* ln1_g      = (const float*)d_in[4];
    const float* ln1_b      = (const float*)d_in[5];
    const float* scorer_w   = (const float*)d_in[6];
    const float* scorer_b   = (const float*)d_in[7];
    const float* conv_w     = (const float*)d_in[8];
    const float* conv_b     = (const float*)d_in[9];
    const float* start      = (const float*)d_in[10];
    const float* wcell1_w   = (const float*)d_in[11];
    const float* wcell1_b   = (const float*)d_in[12];
    const float* wcell2_w   = (const float*)d_in[13];
    const float* wcell2_b   = (const float*)d_in[14];
    const float* ln2_g      = (const float*)d_in[15];
    const float* ln2_b      = (const float*)d_in[16];
    float* out = (float*)d_out;

    cudaFuncSetAttribute(mega, cudaFuncAttributeMaxDynamicSharedMemorySize, SMEM_DYN);
    mega<<<G, NT, SMEM_DYN>>>(sequence, input_mask, w_init, b_init, ln1_g, ln1_b,
                              scorer_w, scorer_b, conv_w, conv_b, start,
                              wcell1_w, wcell1_b, wcell2_w, wcell2_b, ln2_g, ln2_b, out);
}